// round 2
// baseline (speedup 1.0000x reference)
#include <cuda_runtime.h>
#include <cstdint>

// ---------------------------------------------------------------------------
// Problem constants: B=2, S(=Q=K)=2048, D=1024, H=16, HD=64
// ---------------------------------------------------------------------------
#define BATCH 2
#define SLEN  2048
#define DMODEL 1024
#define NHEAD 16
#define HDIM  64
#define NEG_BIG (-3.402823466e38f)
#define LN_EPS 1e-6f

// Scratch (device globals: allocation-free, graph-capture safe)
__device__ float g_q[(size_t)BATCH * NHEAD * SLEN * HDIM];
__device__ float g_k[(size_t)BATCH * NHEAD * SLEN * HDIM];
__device__ float g_v[(size_t)BATCH * NHEAD * SLEN * HDIM];
__device__ float g_x[(size_t)BATCH * SLEN * DMODEL];
__device__ int   g_mask_int32;   // 1 if mask buffer is int32, 0 if uint8

// ---------------------------------------------------------------------------
// Kernel 0: detect mask dtype. If the mask is int32 (values 0/1), all bytes at
// offsets %4 != 0 are zero. Deterministic given inputs.
// ---------------------------------------------------------------------------
__global__ void detect_mask_kernel(const unsigned char* __restrict__ m)
{
    int tid = threadIdx.x;
    unsigned int acc = 0;
    for (int i = tid; i < 4096; i += 32)
        if ((i & 3) != 0) acc |= m[i];
#pragma unroll
    for (int o = 16; o; o >>= 1) acc |= __shfl_xor_sync(0xffffffffu, acc, o);
    if (tid == 0) g_mask_int32 = (acc == 0) ? 1 : 0;
}

// ---------------------------------------------------------------------------
// Kernel 1: QKV projection.  C = A[4096,1024] * W[1024,1024] + bias
// BM=BN=128, BK=16, 256 threads, 8x8 microtile. Scatters into [B][H][S][HD].
// grid = (32, 8, 3)  z selects q/k/v
// ---------------------------------------------------------------------------
__global__ __launch_bounds__(256) void gemm_qkv_kernel(
    const float* __restrict__ A,
    const float* __restrict__ Wq, const float* __restrict__ Wk, const float* __restrict__ Wv,
    const float* __restrict__ Bq, const float* __restrict__ Bk, const float* __restrict__ Bv)
{
    const int K = DMODEL, N = DMODEL;
    const float* Bmat; const float* bias; float* C;
    if (blockIdx.z == 0)      { Bmat = Wq; bias = Bq; C = g_q; }
    else if (blockIdx.z == 1) { Bmat = Wk; bias = Bk; C = g_k; }
    else                      { Bmat = Wv; bias = Bv; C = g_v; }

    __shared__ float As[16][132];   // transposed A tile, padded
    __shared__ float Bs[16][128];

    const int bm = blockIdx.x * 128;
    const int bn = blockIdx.y * 128;
    const int tid = threadIdx.x;
    const int trow = tid >> 4;      // 0..15
    const int tcol = tid & 15;      // 0..15

    float acc[8][8];
#pragma unroll
    for (int i = 0; i < 8; i++)
#pragma unroll
        for (int j = 0; j < 8; j++) acc[i][j] = 0.f;

    for (int k0 = 0; k0 < K; k0 += 16) {
#pragma unroll
        for (int it = 0; it < 2; it++) {
            int l = tid + it * 256;               // 0..511
            int r  = l >> 2, c4 = (l & 3) * 4;    // A tile 128x16
            float4 va = *(const float4*)&A[(size_t)(bm + r) * K + k0 + c4];
            As[c4+0][r] = va.x; As[c4+1][r] = va.y; As[c4+2][r] = va.z; As[c4+3][r] = va.w;
            int rb = l >> 5, cb = (l & 31) * 4;   // B tile 16x128
            float4 vb = *(const float4*)&Bmat[(size_t)(k0 + rb) * N + bn + cb];
            *(float4*)&Bs[rb][cb] = vb;
        }
        __syncthreads();
#pragma unroll
        for (int k = 0; k < 16; k++) {
            float a[8], bb[8];
#pragma unroll
            for (int i = 0; i < 8; i++) a[i]  = As[k][trow * 8 + i];
#pragma unroll
            for (int j = 0; j < 8; j++) bb[j] = Bs[k][tcol * 8 + j];
#pragma unroll
            for (int i = 0; i < 8; i++)
#pragma unroll
                for (int j = 0; j < 8; j++)
                    acc[i][j] = fmaf(a[i], bb[j], acc[i][j]);
        }
        __syncthreads();
    }

    // Epilogue: scatter to [B][H][S][HD]
#pragma unroll
    for (int i = 0; i < 8; i++) {
        int m = bm + trow * 8 + i;
        int b = m >> 11, s = m & (SLEN - 1);
#pragma unroll
        for (int j = 0; j < 8; j++) {
            int n = bn + tcol * 8 + j;
            int h = n >> 6, e = n & (HDIM - 1);
            C[((size_t)((b * NHEAD + h) * SLEN + s)) * HDIM + e] = acc[i][j] + bias[n];
        }
    }
}

// ---------------------------------------------------------------------------
// Kernel 2: per-(b,h,s) LayerNorm over HD=64, scale, optional extra factor.
// One warp per row; lane handles elements lane, lane+32.
// ---------------------------------------------------------------------------
__global__ __launch_bounds__(256) void ln_kernel(int which, const float* __restrict__ scale,
                                                 float extra)
{
    float* buf = (which == 0) ? g_q : g_k;
    int warp = (blockIdx.x * blockDim.x + threadIdx.x) >> 5;
    int lane = threadIdx.x & 31;
    const int nrows = BATCH * NHEAD * SLEN;
    if (warp >= nrows) return;
    float* row = buf + (size_t)warp * HDIM;
    float x0 = row[lane], x1 = row[lane + 32];
    float s = x0 + x1;
#pragma unroll
    for (int o = 16; o; o >>= 1) s += __shfl_xor_sync(0xffffffffu, s, o);
    float mean = s * (1.f / 64.f);
    float d0 = x0 - mean, d1 = x1 - mean;
    float v = d0 * d0 + d1 * d1;
#pragma unroll
    for (int o = 16; o; o >>= 1) v += __shfl_xor_sync(0xffffffffu, v, o);
    float rstd = rsqrtf(v * (1.f / 64.f) + LN_EPS);
    row[lane]      = d0 * rstd * scale[lane]      * extra;
    row[lane + 32] = d1 * rstd * scale[lane + 32] * extra;
}

// ---------------------------------------------------------------------------
// Kernel 3: flash attention per (b, h, q-tile of 64).
// S-gemm 64x64x64, bias+mask, online softmax, PV gemm 64x64x64.
// 256 threads as 16x16; 4x4 microtiles. P reuses the K smem buffer.
// grid = (32, 16, 2)
// ---------------------------------------------------------------------------
__global__ __launch_bounds__(256) void attn_kernel(
    const float* __restrict__ bias, const unsigned char* __restrict__ mask)
{
    const int q0 = blockIdx.x * 64;
    const int h  = blockIdx.y, b = blockIdx.z;
    const float* qh = g_q + ((size_t)(b * NHEAD + h)) * SLEN * HDIM;
    const float* kh = g_k + ((size_t)(b * NHEAD + h)) * SLEN * HDIM;
    const float* vh = g_v + ((size_t)(b * NHEAD + h)) * SLEN * HDIM;
    const float* biasb = bias + (size_t)b * SLEN * SLEN;
    const int mask32 = g_mask_int32;
    const unsigned char* maskb8 = mask + (size_t)b * SLEN * SLEN;
    const int* maskb32 = (const int*)mask + (size_t)b * SLEN * SLEN;

    __shared__ float Qs[64][65];
    __shared__ float KP[64][65];   // K tile, then reused to hold P
    __shared__ float Vs[64][64];

    const int tid = threadIdx.x;
    const int trow = tid >> 4, tcol = tid & 15;
    const int i0 = trow * 4, j0 = tcol * 4;

    // Load Q tile once
    for (int l = tid; l < 1024; l += 256) {
        int r = l >> 4, c4 = (l & 15) * 4;
        float4 v = *(const float4*)&qh[(size_t)(q0 + r) * HDIM + c4];
        Qs[r][c4] = v.x; Qs[r][c4+1] = v.y; Qs[r][c4+2] = v.z; Qs[r][c4+3] = v.w;
    }

    float m_i[4], l_i[4], X[4][4];
#pragma unroll
    for (int ii = 0; ii < 4; ii++) {
        m_i[ii] = NEG_BIG; l_i[ii] = 0.f;
#pragma unroll
        for (int ee = 0; ee < 4; ee++) X[ii][ee] = 0.f;
    }
    __syncthreads();

    for (int kt = 0; kt < SLEN / 64; kt++) {
        const int k0 = kt * 64;
        // load K (padded, scalar) and V (float4) tiles
        for (int l = tid; l < 1024; l += 256) {
            int r = l >> 4, c4 = (l & 15) * 4;
            float4 kv = *(const float4*)&kh[(size_t)(k0 + r) * HDIM + c4];
            KP[r][c4] = kv.x; KP[r][c4+1] = kv.y; KP[r][c4+2] = kv.z; KP[r][c4+3] = kv.w;
            float4 vv = *(const float4*)&vh[(size_t)(k0 + r) * HDIM + c4];
            *(float4*)&Vs[r][c4] = vv;
        }
        __syncthreads();

        // S = Q * K^T  (q already has 1/sqrt(HD) folded in)
        float Sv[4][4];
#pragma unroll
        for (int ii = 0; ii < 4; ii++)
#pragma unroll
            for (int jj = 0; jj < 4; jj++) Sv[ii][jj] = 0.f;
#pragma unroll 8
        for (int e = 0; e < HDIM; e++) {
            float a0 = Qs[i0][e],   a1 = Qs[i0+1][e], a2 = Qs[i0+2][e], a3 = Qs[i0+3][e];
            float b0 = KP[j0][e],   b1 = KP[j0+1][e], b2 = KP[j0+2][e], b3 = KP[j0+3][e];
            Sv[0][0] = fmaf(a0,b0,Sv[0][0]); Sv[0][1] = fmaf(a0,b1,Sv[0][1]);
            Sv[0][2] = fmaf(a0,b2,Sv[0][2]); Sv[0][3] = fmaf(a0,b3,Sv[0][3]);
            Sv[1][0] = fmaf(a1,b0,Sv[1][0]); Sv[1][1] = fmaf(a1,b1,Sv[1][1]);
            Sv[1][2] = fmaf(a1,b2,Sv[1][2]); Sv[1][3] = fmaf(a1,b3,Sv[1][3]);
            Sv[2][0] = fmaf(a2,b0,Sv[2][0]); Sv[2][1] = fmaf(a2,b1,Sv[2][1]);
            Sv[2][2] = fmaf(a2,b2,Sv[2][2]); Sv[2][3] = fmaf(a2,b3,Sv[2][3]);
            Sv[3][0] = fmaf(a3,b0,Sv[3][0]); Sv[3][1] = fmaf(a3,b1,Sv[3][1]);
            Sv[3][2] = fmaf(a3,b2,Sv[3][2]); Sv[3][3] = fmaf(a3,b3,Sv[3][3]);
        }

        // bias + mask (reference order: attn+bias, then where(mask,...,big_neg))
#pragma unroll
        for (int ii = 0; ii < 4; ii++) {
            size_t off = (size_t)(q0 + i0 + ii) * SLEN + k0 + j0;
            float4 bv = *(const float4*)&biasb[off];
            int mx_, my_, mz_, mw_;
            if (mask32) {
                int4 mv = *(const int4*)&maskb32[off];
                mx_ = mv.x; my_ = mv.y; mz_ = mv.z; mw_ = mv.w;
            } else {
                uchar4 mv = *(const uchar4*)&maskb8[off];
                mx_ = mv.x; my_ = mv.y; mz_ = mv.z; mw_ = mv.w;
            }
            Sv[ii][0] = mx_ ? Sv[ii][0] + bv.x : NEG_BIG;
            Sv[ii][1] = my_ ? Sv[ii][1] + bv.y : NEG_BIG;
            Sv[ii][2] = mz_ ? Sv[ii][2] + bv.z : NEG_BIG;
            Sv[ii][3] = mw_ ? Sv[ii][3] + bv.w : NEG_BIG;
        }

        // online softmax (row groups = 16 lanes sharing trow)
#pragma unroll
        for (int ii = 0; ii < 4; ii++) {
            float mx = fmaxf(fmaxf(Sv[ii][0], Sv[ii][1]), fmaxf(Sv[ii][2], Sv[ii][3]));
#pragma unroll
            for (int o = 8; o; o >>= 1) mx = fmaxf(mx, __shfl_xor_sync(0xffffffffu, mx, o));
            float mnew = fmaxf(m_i[ii], mx);
            float corr = __expf(m_i[ii] - mnew);
            m_i[ii] = mnew;
            float rs = 0.f;
#pragma unroll
            for (int jj = 0; jj < 4; jj++) {
                float p = __expf(Sv[ii][jj] - mnew);
                Sv[ii][jj] = p;
                rs += p;
            }
#pragma unroll
            for (int o = 8; o; o >>= 1) rs += __shfl_xor_sync(0xffffffffu, rs, o);
            l_i[ii] = l_i[ii] * corr + rs;
#pragma unroll
            for (int ee = 0; ee < 4; ee++) X[ii][ee] *= corr;
        }

        __syncthreads();           // done reading KP as K
        // store P into KP as [i][j]
#pragma unroll
        for (int ii = 0; ii < 4; ii++)
#pragma unroll
            for (int jj = 0; jj < 4; jj++)
                KP[i0 + ii][j0 + jj] = Sv[ii][jj];
        __syncthreads();

        // X += P * V
#pragma unroll 8
        for (int j = 0; j < 64; j++) {
            float p0 = KP[i0][j], p1 = KP[i0+1][j], p2 = KP[i0+2][j], p3 = KP[i0+3][j];
            float4 vv = *(const float4*)&Vs[j][j0];
            X[0][0] = fmaf(p0, vv.x, X[0][0]); X[0][1] = fmaf(p0, vv.y, X[0][1]);
            X[0][2] = fmaf(p0, vv.z, X[0][2]); X[0][3] = fmaf(p0, vv.w, X[0][3]);
            X[1][0] = fmaf(p1, vv.x, X[1][0]); X[1][1] = fmaf(p1, vv.y, X[1][1]);
            X[1][2] = fmaf(p1, vv.z, X[1][2]); X[1][3] = fmaf(p1, vv.w, X[1][3]);
            X[2][0] = fmaf(p2, vv.x, X[2][0]); X[2][1] = fmaf(p2, vv.y, X[2][1]);
            X[2][2] = fmaf(p2, vv.z, X[2][2]); X[2][3] = fmaf(p2, vv.w, X[2][3]);
            X[3][0] = fmaf(p3, vv.x, X[3][0]); X[3][1] = fmaf(p3, vv.y, X[3][1]);
            X[3][2] = fmaf(p3, vv.z, X[3][2]); X[3][3] = fmaf(p3, vv.w, X[3][3]);
        }
        __syncthreads();           // before next tile overwrites KP/Vs
    }

    // normalize and write x in [B][S][H*HD] layout
#pragma unroll
    for (int ii = 0; ii < 4; ii++) {
        float inv = 1.0f / l_i[ii];
        float4 o;
        o.x = X[ii][0] * inv; o.y = X[ii][1] * inv;
        o.z = X[ii][2] * inv; o.w = X[ii][3] * inv;
        size_t idx = ((size_t)(b * SLEN + q0 + i0 + ii)) * DMODEL + h * HDIM + j0;
        *(float4*)&g_x[idx] = o;
    }
}

// ---------------------------------------------------------------------------
// Kernel 4: output projection. out = g_x[4096,1024] * wo[1024,1024] + bo
// grid = (32, 8)
// ---------------------------------------------------------------------------
__global__ __launch_bounds__(256) void gemm_out_kernel(
    const float* __restrict__ Wo, const float* __restrict__ Bo, float* __restrict__ out)
{
    const int K = DMODEL, N = DMODEL;
    const float* A = g_x;

    __shared__ float As[16][132];
    __shared__ float Bs[16][128];

    const int bm = blockIdx.x * 128;
    const int bn = blockIdx.y * 128;
    const int tid = threadIdx.x;
    const int trow = tid >> 4;
    const int tcol = tid & 15;

    float acc[8][8];
#pragma unroll
    for (int i = 0; i < 8; i++)
#pragma unroll
        for (int j = 0; j < 8; j++) acc[i][j] = 0.f;

    for (int k0 = 0; k0 < K; k0 += 16) {
#pragma unroll
        for (int it = 0; it < 2; it++) {
            int l = tid + it * 256;
            int r  = l >> 2, c4 = (l & 3) * 4;
            float4 va = *(const float4*)&A[(size_t)(bm + r) * K + k0 + c4];
            As[c4+0][r] = va.x; As[c4+1][r] = va.y; As[c4+2][r] = va.z; As[c4+3][r] = va.w;
            int rb = l >> 5, cb = (l & 31) * 4;
            float4 vb = *(const float4*)&Wo[(size_t)(k0 + rb) * N + bn + cb];
            *(float4*)&Bs[rb][cb] = vb;
        }
        __syncthreads();
#pragma unroll
        for (int k = 0; k < 16; k++) {
            float a[8], bb[8];
#pragma unroll
            for (int i = 0; i < 8; i++) a[i]  = As[k][trow * 8 + i];
#pragma unroll
            for (int j = 0; j < 8; j++) bb[j] = Bs[k][tcol * 8 + j];
#pragma unroll
            for (int i = 0; i < 8; i++)
#pragma unroll
                for (int j = 0; j < 8; j++)
                    acc[i][j] = fmaf(a[i], bb[j], acc[i][j]);
        }
        __syncthreads();
    }

#pragma unroll
    for (int i = 0; i < 8; i++) {
        int m = bm + trow * 8 + i;
#pragma unroll
        for (int j = 0; j < 8; j++) {
            int n = bn + tcol * 8 + j;
            out[(size_t)m * N + n] = acc[i][j] + Bo[n];
        }
    }
}

// ---------------------------------------------------------------------------
// Launch
// ---------------------------------------------------------------------------
extern "C" void kernel_launch(void* const* d_in, const int* in_sizes, int n_in,
                              void* d_out, int out_size)
{
    const float*         inputs_q = (const float*)d_in[0];
    const float*         bias     = (const float*)d_in[1];
    const unsigned char* mask     = (const unsigned char*)d_in[2];
    const float*         wq       = (const float*)d_in[3];
    const float*         bq       = (const float*)d_in[4];
    const float*         wk       = (const float*)d_in[5];
    const float*         bk       = (const float*)d_in[6];
    const float*         wv       = (const float*)d_in[7];
    const float*         bv       = (const float*)d_in[8];
    const float*         q_scale  = (const float*)d_in[9];
    const float*         k_scale  = (const float*)d_in[10];
    const float*         wo       = (const float*)d_in[11];
    const float*         bo       = (const float*)d_in[12];
    float*               out      = (float*)d_out;

    // 0) mask dtype detection (int32 vs uint8)
    detect_mask_kernel<<<1, 32>>>(mask);

    // 1) QKV projections
    gemm_qkv_kernel<<<dim3(32, 8, 3), 256>>>(inputs_q, wq, wk, wv, bq, bk, bv);

    // 2) QK layernorm (q also gets 1/sqrt(HD) = 0.125)
    const int ln_rows = BATCH * NHEAD * SLEN;          // 65536 rows, 8 warps/block
    ln_kernel<<<ln_rows / 8, 256>>>(0, q_scale, 0.125f);
    ln_kernel<<<ln_rows / 8, 256>>>(1, k_scale, 1.0f);

    // 3) flash attention
    attn_kernel<<<dim3(SLEN / 64, NHEAD, BATCH), 256>>>(bias, mask);

    // 4) output projection
    gemm_out_kernel<<<dim3(32, 8), 256>>>(wo, bo, out);
}

// round 3
// speedup vs baseline: 3.0266x; 3.0266x over previous
#include <cuda_runtime.h>
#include <cstdint>

#define BATCH 2
#define SLEN  2048
#define DMODEL 1024
#define NHEAD 16
#define HDIM  64
#define NEG_BIG (-3.402823466e38f)
#define LN_EPS 1e-6f

__device__ float g_q[(size_t)BATCH * NHEAD * SLEN * HDIM];
__device__ float g_k[(size_t)BATCH * NHEAD * SLEN * HDIM];
__device__ float g_v[(size_t)BATCH * NHEAD * SLEN * HDIM];
__device__ float g_x[(size_t)BATCH * SLEN * DMODEL];
__device__ float g_bm[(size_t)BATCH * SLEN * SLEN];
__device__ int   g_mask_int32;

__device__ __forceinline__ float tf32f(float f) {
    unsigned u;
    asm("cvt.rna.tf32.f32 %0, %1;" : "=r"(u) : "f"(f));
    return __uint_as_float(u);
}
__device__ __forceinline__ void round4(float4& v) {
    v.x = tf32f(v.x); v.y = tf32f(v.y); v.z = tf32f(v.z); v.w = tf32f(v.w);
}
__device__ __forceinline__ void mma_tf32(float4& c,
    unsigned a0, unsigned a1, unsigned a2, unsigned a3,
    unsigned b0, unsigned b1)
{
    asm volatile(
        "mma.sync.aligned.m16n8k8.row.col.f32.tf32.tf32.f32 "
        "{%0,%1,%2,%3}, {%4,%5,%6,%7}, {%8,%9}, {%0,%1,%2,%3};"
        : "+f"(c.x), "+f"(c.y), "+f"(c.z), "+f"(c.w)
        : "r"(a0), "r"(a1), "r"(a2), "r"(a3), "r"(b0), "r"(b1));
}

// --------------------------------------------------------------------------
__global__ void detect_mask_kernel(const unsigned char* __restrict__ m)
{
    int tid = threadIdx.x;
    unsigned int acc = 0;
    for (int i = tid; i < 4096; i += 32)
        if ((i & 3) != 0) acc |= m[i];
#pragma unroll
    for (int o = 16; o; o >>= 1) acc |= __shfl_xor_sync(0xffffffffu, acc, o);
    if (tid == 0) g_mask_int32 = (acc == 0) ? 1 : 0;
}

__global__ __launch_bounds__(256) void prep_bm_kernel(
    const float* __restrict__ bias, const unsigned char* __restrict__ mask)
{
    size_t i = ((size_t)blockIdx.x * blockDim.x + threadIdx.x) * 4;
    const size_t N = (size_t)BATCH * SLEN * SLEN;
    if (i >= N) return;
    float4 bv = *(const float4*)&bias[i];
    int mx, my, mz, mw;
    if (g_mask_int32) {
        int4 m = *(const int4*)((const int*)mask + i);
        mx = m.x; my = m.y; mz = m.z; mw = m.w;
    } else {
        uchar4 m = *(const uchar4*)(mask + i);
        mx = m.x; my = m.y; mz = m.z; mw = m.w;
    }
    float4 o;
    o.x = mx ? bv.x : NEG_BIG;
    o.y = my ? bv.y : NEG_BIG;
    o.z = mz ? bv.z : NEG_BIG;
    o.w = mw ? bv.w : NEG_BIG;
    *(float4*)&g_bm[i] = o;
}

// --------------------------------------------------------------------------
// tf32 GEMM: 128x128 block, 8 warps (4x2) of 32x64, K-step 32.
// MODE 0: QKV (selects W/bias/output by blockIdx.z, scatters to [B][H][S][HD])
// MODE 1: out-proj, reads g_x, writes Cout row-major
// --------------------------------------------------------------------------
template<int MODE>
__global__ __launch_bounds__(256) void gemm_tc(
    const float* __restrict__ A,
    const float* __restrict__ W0, const float* __restrict__ W1, const float* __restrict__ W2,
    const float* __restrict__ b0_, const float* __restrict__ b1_, const float* __restrict__ b2_,
    float* __restrict__ Cout)
{
    const float* W; const float* bias; float* C;
    if (MODE == 0) {
        if (blockIdx.z == 0)      { W = W0; bias = b0_; C = g_q; }
        else if (blockIdx.z == 1) { W = W1; bias = b1_; C = g_k; }
        else                      { W = W2; bias = b2_; C = g_v; }
    } else {
        W = W0; bias = b0_; C = Cout;
    }

    __shared__ float As[128][36];
    __shared__ float Bs[32][136];

    const int tid  = threadIdx.x;
    const int warp = tid >> 5, lane = tid & 31;
    const int grp  = lane >> 2, t4 = lane & 3;
    const int wm   = warp >> 1, wn = warp & 1;
    const int bm   = blockIdx.x * 128, bn = blockIdx.y * 128;

    float4 acc[2][8];
#pragma unroll
    for (int mt = 0; mt < 2; mt++)
#pragma unroll
        for (int nt = 0; nt < 8; nt++) acc[mt][nt] = make_float4(0.f, 0.f, 0.f, 0.f);

    for (int k0 = 0; k0 < DMODEL; k0 += 32) {
#pragma unroll
        for (int it = 0; it < 4; it++) {
            int f = tid + it * 256;
            int r = f >> 3, c4 = (f & 7) * 4;
            float4 va = *(const float4*)&A[(size_t)(bm + r) * DMODEL + k0 + c4];
            round4(va);
            *(float4*)&As[r][c4] = va;
            int rb = f >> 5, cb = (f & 31) * 4;
            float4 vb = *(const float4*)&W[(size_t)(k0 + rb) * DMODEL + bn + cb];
            round4(vb);
            *(float4*)&Bs[rb][cb] = vb;
        }
        __syncthreads();

#pragma unroll
        for (int kk = 0; kk < 32; kk += 8) {
            unsigned a[2][4];
#pragma unroll
            for (int mt = 0; mt < 2; mt++) {
                int m = wm * 32 + mt * 16 + grp;
                a[mt][0] = __float_as_uint(As[m][kk + t4]);
                a[mt][1] = __float_as_uint(As[m + 8][kk + t4]);
                a[mt][2] = __float_as_uint(As[m][kk + t4 + 4]);
                a[mt][3] = __float_as_uint(As[m + 8][kk + t4 + 4]);
            }
            unsigned bf[8][2];
#pragma unroll
            for (int nt = 0; nt < 8; nt++) {
                int n = wn * 64 + nt * 8 + grp;
                bf[nt][0] = __float_as_uint(Bs[kk + t4][n]);
                bf[nt][1] = __float_as_uint(Bs[kk + t4 + 4][n]);
            }
#pragma unroll
            for (int mt = 0; mt < 2; mt++)
#pragma unroll
                for (int nt = 0; nt < 8; nt++)
                    mma_tf32(acc[mt][nt], a[mt][0], a[mt][1], a[mt][2], a[mt][3],
                             bf[nt][0], bf[nt][1]);
        }
        __syncthreads();
    }

#pragma unroll
    for (int mt = 0; mt < 2; mt++) {
#pragma unroll
        for (int nt = 0; nt < 8; nt++) {
            int m = bm + wm * 32 + mt * 16 + grp;
            int n = bn + wn * 64 + nt * 8 + 2 * t4;
            float bx = bias[n], by = bias[n + 1];
            float2 lo = make_float2(acc[mt][nt].x + bx, acc[mt][nt].y + by);
            float2 hi = make_float2(acc[mt][nt].z + bx, acc[mt][nt].w + by);
            if (MODE == 0) {
                int bb = m >> 11, hh = n >> 6, e = n & (HDIM - 1);
                int s_lo = m & (SLEN - 1), s_hi = (m + 8) & (SLEN - 1);
                *(float2*)&C[((size_t)((bb * NHEAD + hh) * SLEN + s_lo)) * HDIM + e] = lo;
                *(float2*)&C[((size_t)((bb * NHEAD + hh) * SLEN + s_hi)) * HDIM + e] = hi;
            } else {
                *(float2*)&C[(size_t)m * DMODEL + n] = lo;
                *(float2*)&C[(size_t)(m + 8) * DMODEL + n] = hi;
            }
        }
    }
}

// --------------------------------------------------------------------------
__global__ __launch_bounds__(256) void ln_kernel(int which, const float* __restrict__ scale,
                                                 float extra)
{
    float* buf = (which == 0) ? g_q : g_k;
    int warp = (blockIdx.x * blockDim.x + threadIdx.x) >> 5;
    int lane = threadIdx.x & 31;
    const int nrows = BATCH * NHEAD * SLEN;
    if (warp >= nrows) return;
    float* row = buf + (size_t)warp * HDIM;
    float x0 = row[lane], x1 = row[lane + 32];
    float s = x0 + x1;
#pragma unroll
    for (int o = 16; o; o >>= 1) s += __shfl_xor_sync(0xffffffffu, s, o);
    float mean = s * (1.f / 64.f);
    float d0 = x0 - mean, d1 = x1 - mean;
    float v = d0 * d0 + d1 * d1;
#pragma unroll
    for (int o = 16; o; o >>= 1) v += __shfl_xor_sync(0xffffffffu, v, o);
    float rstd = rsqrtf(v * (1.f / 64.f) + LN_EPS);
    row[lane]      = d0 * rstd * scale[lane]      * extra;
    row[lane + 32] = d1 * rstd * scale[lane + 32] * extra;
}

// --------------------------------------------------------------------------
// tf32 flash attention. 128 q-rows/block, 8 warps x m16, kv tiles of 64.
// --------------------------------------------------------------------------
__global__ __launch_bounds__(256) void attn_tc()
{
    extern __shared__ float smdyn[];
    float (*Ks)[68] = (float(*)[68])smdyn;
    float (*Vs)[72] = (float(*)[72])(smdyn + 64 * 68);
    float (*Ps)[68] = (float(*)[68])(smdyn + 64 * 68 + 64 * 72);

    const int tid  = threadIdx.x;
    const int warp = tid >> 5, lane = tid & 31;
    const int grp  = lane >> 2, t4 = lane & 3;
    const int m0   = warp * 16;
    const int q0   = blockIdx.x * 128;
    const int h    = blockIdx.y, b = blockIdx.z;

    const float* qh = g_q + ((size_t)(b * NHEAD + h)) * SLEN * HDIM;
    const float* kh = g_k + ((size_t)(b * NHEAD + h)) * SLEN * HDIM;
    const float* vh = g_v + ((size_t)(b * NHEAD + h)) * SLEN * HDIM;
    const float* bmb = g_bm + (size_t)b * SLEN * SLEN;

#pragma unroll
    for (int it = 0; it < 8; it++) {
        int f = tid + it * 256;
        int r = f >> 4, c4 = (f & 15) * 4;
        float4 v = *(const float4*)&qh[(size_t)(q0 + r) * HDIM + c4];
        round4(v);
        *(float4*)&Ps[r][c4] = v;
    }
    __syncthreads();
    unsigned qa[8][4];
#pragma unroll
    for (int kk = 0; kk < 8; kk++) {
        qa[kk][0] = __float_as_uint(Ps[m0 + grp][kk * 8 + t4]);
        qa[kk][1] = __float_as_uint(Ps[m0 + grp + 8][kk * 8 + t4]);
        qa[kk][2] = __float_as_uint(Ps[m0 + grp][kk * 8 + t4 + 4]);
        qa[kk][3] = __float_as_uint(Ps[m0 + grp + 8][kk * 8 + t4 + 4]);
    }
    __syncthreads();

    float4 X[8];
#pragma unroll
    for (int nt = 0; nt < 8; nt++) X[nt] = make_float4(0.f, 0.f, 0.f, 0.f);
    float m_lo = NEG_BIG, m_hi = NEG_BIG, l_lo = 0.f, l_hi = 0.f;

    const float* bm_lo_base = &bmb[(size_t)(q0 + m0 + grp) * SLEN];
    const float* bm_hi_base = bm_lo_base + (size_t)8 * SLEN;

    for (int kt = 0; kt < SLEN / 64; kt++) {
        const int k0 = kt * 64;
#pragma unroll
        for (int it = 0; it < 4; it++) {
            int f = tid + it * 256;
            int r = f >> 4, c4 = (f & 15) * 4;
            float4 kv = *(const float4*)&kh[(size_t)(k0 + r) * HDIM + c4];
            round4(kv);
            *(float4*)&Ks[r][c4] = kv;
            float4 vv = *(const float4*)&vh[(size_t)(k0 + r) * HDIM + c4];
            round4(vv);
            *(float4*)&Vs[r][c4] = vv;
        }
        __syncthreads();

        float4 s[8];
#pragma unroll
        for (int nt = 0; nt < 8; nt++) s[nt] = make_float4(0.f, 0.f, 0.f, 0.f);
#pragma unroll
        for (int kk = 0; kk < 8; kk++) {
#pragma unroll
            for (int nt = 0; nt < 8; nt++) {
                unsigned kb0 = __float_as_uint(Ks[nt * 8 + grp][kk * 8 + t4]);
                unsigned kb1 = __float_as_uint(Ks[nt * 8 + grp][kk * 8 + t4 + 4]);
                mma_tf32(s[nt], qa[kk][0], qa[kk][1], qa[kk][2], qa[kk][3], kb0, kb1);
            }
        }

        float mx_lo = NEG_BIG, mx_hi = NEG_BIG;
#pragma unroll
        for (int nt = 0; nt < 8; nt++) {
            float2 blo = *(const float2*)&bm_lo_base[k0 + nt * 8 + 2 * t4];
            float2 bhi = *(const float2*)&bm_hi_base[k0 + nt * 8 + 2 * t4];
            s[nt].x += blo.x; s[nt].y += blo.y;
            s[nt].z += bhi.x; s[nt].w += bhi.y;
            mx_lo = fmaxf(mx_lo, fmaxf(s[nt].x, s[nt].y));
            mx_hi = fmaxf(mx_hi, fmaxf(s[nt].z, s[nt].w));
        }
        mx_lo = fmaxf(mx_lo, __shfl_xor_sync(0xffffffffu, mx_lo, 1));
        mx_lo = fmaxf(mx_lo, __shfl_xor_sync(0xffffffffu, mx_lo, 2));
        mx_hi = fmaxf(mx_hi, __shfl_xor_sync(0xffffffffu, mx_hi, 1));
        mx_hi = fmaxf(mx_hi, __shfl_xor_sync(0xffffffffu, mx_hi, 2));

        float mn_lo = fmaxf(m_lo, mx_lo), mn_hi = fmaxf(m_hi, mx_hi);
        float cor_lo = __expf(m_lo - mn_lo), cor_hi = __expf(m_hi - mn_hi);
        m_lo = mn_lo; m_hi = mn_hi;

        float rs_lo = 0.f, rs_hi = 0.f;
#pragma unroll
        for (int nt = 0; nt < 8; nt++) {
            s[nt].x = __expf(s[nt].x - mn_lo);
            s[nt].y = __expf(s[nt].y - mn_lo);
            s[nt].z = __expf(s[nt].z - mn_hi);
            s[nt].w = __expf(s[nt].w - mn_hi);
            rs_lo += s[nt].x + s[nt].y;
            rs_hi += s[nt].z + s[nt].w;
        }
        rs_lo += __shfl_xor_sync(0xffffffffu, rs_lo, 1);
        rs_lo += __shfl_xor_sync(0xffffffffu, rs_lo, 2);
        rs_hi += __shfl_xor_sync(0xffffffffu, rs_hi, 1);
        rs_hi += __shfl_xor_sync(0xffffffffu, rs_hi, 2);
        l_lo = l_lo * cor_lo + rs_lo;
        l_hi = l_hi * cor_hi + rs_hi;
#pragma unroll
        for (int nt = 0; nt < 8; nt++) {
            X[nt].x *= cor_lo; X[nt].y *= cor_lo;
            X[nt].z *= cor_hi; X[nt].w *= cor_hi;
        }

#pragma unroll
        for (int nt = 0; nt < 8; nt++) {
            Ps[m0 + grp][nt * 8 + 2 * t4]         = tf32f(s[nt].x);
            Ps[m0 + grp][nt * 8 + 2 * t4 + 1]     = tf32f(s[nt].y);
            Ps[m0 + grp + 8][nt * 8 + 2 * t4]     = tf32f(s[nt].z);
            Ps[m0 + grp + 8][nt * 8 + 2 * t4 + 1] = tf32f(s[nt].w);
        }
        __syncwarp();

#pragma unroll
        for (int kk = 0; kk < 8; kk++) {
            unsigned pa0 = __float_as_uint(Ps[m0 + grp][kk * 8 + t4]);
            unsigned pa1 = __float_as_uint(Ps[m0 + grp + 8][kk * 8 + t4]);
            unsigned pa2 = __float_as_uint(Ps[m0 + grp][kk * 8 + t4 + 4]);
            unsigned pa3 = __float_as_uint(Ps[m0 + grp + 8][kk * 8 + t4 + 4]);
#pragma unroll
            for (int nt = 0; nt < 8; nt++) {
                unsigned vb0 = __float_as_uint(Vs[kk * 8 + t4][nt * 8 + grp]);
                unsigned vb1 = __float_as_uint(Vs[kk * 8 + t4 + 4][nt * 8 + grp]);
                mma_tf32(X[nt], pa0, pa1, pa2, pa3, vb0, vb1);
            }
        }
        __syncthreads();
    }

    float il_lo = 1.f / l_lo, il_hi = 1.f / l_hi;
    int r_lo = q0 + m0 + grp, r_hi = r_lo + 8;
#pragma unroll
    for (int nt = 0; nt < 8; nt++) {
        int col = h * HDIM + nt * 8 + 2 * t4;
        float2 lo = make_float2(X[nt].x * il_lo, X[nt].y * il_lo);
        float2 hi = make_float2(X[nt].z * il_hi, X[nt].w * il_hi);
        *(float2*)&g_x[(size_t)(b * SLEN + r_lo) * DMODEL + col] = lo;
        *(float2*)&g_x[(size_t)(b * SLEN + r_hi) * DMODEL + col] = hi;
    }
}

// helper to get device pointer of g_x for MODE 1 A operand
__global__ void noop_kernel() {}

extern "C" void kernel_launch(void* const* d_in, const int* in_sizes, int n_in,
                              void* d_out, int out_size)
{
    const float*         inputs_q = (const float*)d_in[0];
    const float*         bias     = (const float*)d_in[1];
    const unsigned char* mask     = (const unsigned char*)d_in[2];
    const float*         wq       = (const float*)d_in[3];
    const float*         bq       = (const float*)d_in[4];
    const float*         wk       = (const float*)d_in[5];
    const float*         bk       = (const float*)d_in[6];
    const float*         wv       = (const float*)d_in[7];
    const float*         bv       = (const float*)d_in[8];
    const float*         q_scale  = (const float*)d_in[9];
    const float*         k_scale  = (const float*)d_in[10];
    const float*         wo       = (const float*)d_in[11];
    const float*         bo       = (const float*)d_in[12];
    float*               out      = (float*)d_out;

    static bool attr_set = false;
    if (!attr_set) {
        cudaFuncSetAttribute(attn_tc, cudaFuncAttributeMaxDynamicSharedMemorySize, 70656);
        attr_set = true;
    }
    static float* gx_ptr = nullptr;
    if (!gx_ptr) cudaGetSymbolAddress((void**)&gx_ptr, g_x);

    detect_mask_kernel<<<1, 32>>>(mask);
    {
        const size_t N = (size_t)BATCH * SLEN * SLEN;
        int blocks = (int)((N / 4 + 255) / 256);
        prep_bm_kernel<<<blocks, 256>>>(bias, mask);
    }

    gemm_tc<0><<<dim3(32, 8, 3), 256>>>(inputs_q, wq, wk, wv, bq, bk, bv, nullptr);

    const int ln_rows = BATCH * NHEAD * SLEN;
    ln_kernel<<<ln_rows / 8, 256>>>(0, q_scale, 0.125f);
    ln_kernel<<<ln_rows / 8, 256>>>(1, k_scale, 1.0f);

    attn_tc<<<dim3(SLEN / 128, NHEAD, BATCH), 256, 70656>>>();

    gemm_tc<1><<<dim3(32, 8), 256>>>(gx_ptr, wo, nullptr, nullptr, bo, nullptr, nullptr, out);
}